// round 2
// baseline (speedup 1.0000x reference)
#include <cuda_runtime.h>
#include <cuda_bf16.h>
#include <cstdint>

// Problem: y[b,e] = relu(sum_a action[b,a] * conv_w[e,a] + conv_b[e])
// out[b,e,h,w] = y[b,e] broadcast over 64x64 spatial.
// B=128, A=256, E=256, H=W=64. Output fp32, 512 MB -> pure HBM-write-bound.

#define B_DIM   128
#define A_DIM   256
#define E_DIM   256
#define HW      4096                 // 64*64
#define NPLANES (B_DIM * E_DIM)      // 32768
#define FILL_GRID (148 * 8)          // one full wave at occ=8 (persistent)

// Scratch for the small GEMM result (128 KB). Device global: allowed.
__device__ float g_y[NPLANES];

// ---------------------------------------------------------------------------
// Kernel 1: tiny GEMM + bias + relu. One block per batch row, one thread per
// output channel e. action row staged in shared; conv_w read via float4 LDG.
// Total work ~17 MFLOP: irrelevant next to the 512 MB fill.
// ---------------------------------------------------------------------------
__global__ __launch_bounds__(E_DIM)
void action_gemm_kernel(const float* __restrict__ action,
                        const float* __restrict__ conv_w,
                        const float* __restrict__ conv_b)
{
    __shared__ float s_act[A_DIM];
    const int b = blockIdx.x;      // 0..127
    const int e = threadIdx.x;     // 0..255

    s_act[e] = action[b * A_DIM + e];
    __syncthreads();

    const float4* w4 = reinterpret_cast<const float4*>(conv_w + e * A_DIM);
    const float4* a4 = reinterpret_cast<const float4*>(s_act);

    float sum = 0.0f;
#pragma unroll
    for (int i = 0; i < A_DIM / 4; ++i) {
        float4 wv = w4[i];
        float4 av = a4[i];
        sum = fmaf(wv.x, av.x, sum);
        sum = fmaf(wv.y, av.y, sum);
        sum = fmaf(wv.z, av.z, sum);
        sum = fmaf(wv.w, av.w, sum);
    }
    sum += conv_b[e];
    g_y[b * E_DIM + e] = fmaxf(sum, 0.0f);
}

// ---------------------------------------------------------------------------
// Kernel 2: persistent broadcast fill. Single wave (1184 blocks), each block
// grid-strides over planes (~28 each). The next plane's y value is prefetched
// one iteration ahead so its L2 latency hides behind 16 KB of streaming
// STG.128.cs stores. Each warp writes contiguous 512 B segments -> full
// 128B-line write coalescing.
// ---------------------------------------------------------------------------
__global__ __launch_bounds__(256)
void broadcast_fill_kernel(float4* __restrict__ out)
{
    const int t = threadIdx.x;
    int plane = blockIdx.x;
    if (plane >= NPLANES) return;

    float v = g_y[plane];

    while (true) {
        const int next = plane + FILL_GRID;
        float vn = 0.0f;
        if (next < NPLANES) vn = g_y[next];        // prefetch next plane's value

        const float4 v4 = make_float4(v, v, v, v);
        float4* p = out + (size_t)plane * (HW / 4); // 1024 float4 per plane

        __stcs(p + t,        v4);
        __stcs(p + t + 256,  v4);
        __stcs(p + t + 512,  v4);
        __stcs(p + t + 768,  v4);

        if (next >= NPLANES) break;
        plane = next;
        v = vn;
    }
}

extern "C" void kernel_launch(void* const* d_in, const int* in_sizes, int n_in,
                              void* d_out, int out_size)
{
    const float* action = (const float*)d_in[0];   // [128, 256]
    const float* conv_w = (const float*)d_in[1];   // [256, 256]
    const float* conv_b = (const float*)d_in[2];   // [256]
    float4* out = (float4*)d_out;                  // [128, 256, 64, 64] fp32

    action_gemm_kernel<<<B_DIM, E_DIM>>>(action, conv_w, conv_b);
    broadcast_fill_kernel<<<FILL_GRID, 256>>>(out);
}

// round 3
// speedup vs baseline: 1.2988x; 1.2988x over previous
#include <cuda_runtime.h>
#include <cuda_bf16.h>
#include <cstdint>

// Problem: y[b,e] = relu(sum_a action[b,a] * conv_w[e,a] + conv_b[e])
// out[b,e,h,w] = y[b,e] broadcast over 64x64 spatial.
// B=128, A=256, E=256, H=W=64. Output fp32, 512 MB -> pure HBM-write-bound.
//
// Single fused kernel: one block per (b,e) plane. Each warp redundantly
// computes the 256-length dot product (inputs are L2-resident: 384 KB total),
// warp-shuffle reduces, then streams 16 KB of STG.128.cs. No smem, no
// __syncthreads, no scratch, no second launch.

#define B_DIM   128
#define A_DIM   256
#define E_DIM   256
#define HW      4096                 // 64*64
#define NPLANES (B_DIM * E_DIM)      // 32768

__global__ __launch_bounds__(256)
void fused_embed_fill_kernel(const float*  __restrict__ action,
                             const float*  __restrict__ conv_w,
                             const float*  __restrict__ conv_b,
                             float4*       __restrict__ out)
{
    const int plane = blockIdx.x;          // b*256 + e
    const int b = plane >> 8;
    const int e = plane & 255;
    const int t    = threadIdx.x;
    const int lane = t & 31;

    // --- per-warp redundant dot product over A=256 -------------------------
    // Each lane handles 8 elements as two float4s: [lane*4 .. lane*4+3] and
    // [128 + lane*4 .. 128 + lane*4+3]. Coalesced; L2 hits after first wave.
    const float4* a4 = reinterpret_cast<const float4*>(action + b * A_DIM);
    const float4* w4 = reinterpret_cast<const float4*>(conv_w + e * A_DIM);

    float4 av0 = a4[lane];
    float4 av1 = a4[lane + 32];
    float4 wv0 = w4[lane];
    float4 wv1 = w4[lane + 32];

    float s;
    s = av0.x * wv0.x;
    s = fmaf(av0.y, wv0.y, s);
    s = fmaf(av0.z, wv0.z, s);
    s = fmaf(av0.w, wv0.w, s);
    s = fmaf(av1.x, wv1.x, s);
    s = fmaf(av1.y, wv1.y, s);
    s = fmaf(av1.z, wv1.z, s);
    s = fmaf(av1.w, wv1.w, s);

    // warp reduction -> every lane holds the full sum
    s += __shfl_xor_sync(0xFFFFFFFF, s, 16);
    s += __shfl_xor_sync(0xFFFFFFFF, s, 8);
    s += __shfl_xor_sync(0xFFFFFFFF, s, 4);
    s += __shfl_xor_sync(0xFFFFFFFF, s, 2);
    s += __shfl_xor_sync(0xFFFFFFFF, s, 1);

    const float v = fmaxf(s + __ldg(conv_b + e), 0.0f);
    const float4 v4 = make_float4(v, v, v, v);

    // --- stream 16 KB plane fill ------------------------------------------
    float4* p = out + (size_t)plane * (HW / 4);   // 1024 float4 per plane

    __stcs(p + t,        v4);
    __stcs(p + t + 256,  v4);
    __stcs(p + t + 512,  v4);
    __stcs(p + t + 768,  v4);
}

extern "C" void kernel_launch(void* const* d_in, const int* in_sizes, int n_in,
                              void* d_out, int out_size)
{
    const float* action = (const float*)d_in[0];   // [128, 256]
    const float* conv_w = (const float*)d_in[1];   // [256, 256]
    const float* conv_b = (const float*)d_in[2];   // [256]
    float4* out = (float4*)d_out;                  // [128, 256, 64, 64] fp32

    fused_embed_fill_kernel<<<NPLANES, 256>>>(action, conv_w, conv_b, out);
}